// round 10
// baseline (speedup 1.0000x reference)
#include <cuda_runtime.h>
#include <cuda_bf16.h>
#include <cstdint>

#define BB 2
#define NN 384
#define DD 256
#define DDIRC 128
#define DSIMC 64
#define EPSF 1e-6f
#define DELTAF 1e-6f

// ---------------- scratch (static device globals; no allocations) ----------------
__device__ float g_q [BB*NN*DSIMC];
__device__ float g_k [BB*NN*DSIMC];
__device__ float g_qd[BB*NN*DDIRC];
__device__ float g_kd[BB*NN*DDIRC];
__device__ float g_s [BB*NN*NN];
__device__ float g_m [BB*NN];
__device__ double g_stats[BB*2];
__device__ __nv_bfloat16 g_vdt[DD*DDIRC];   // Vdt[d][r] = Vd[r][d], bf16

// ---------------- K0: zero stats + transpose/convert Vd ----------------
__global__ void k0_init(const float* __restrict__ Vd) {
    int idx = blockIdx.x*blockDim.x + threadIdx.x;
    if (idx < BB*2) g_stats[idx] = 0.0;
    for (int i = idx; i < DD*DDIRC; i += gridDim.x*blockDim.x) {
        int d = i / DDIRC, r = i % DDIRC;
        g_vdt[i] = __float2bfloat16(Vd[r*DD + d]);
    }
}

// ---------------- K1: projections q,k,qd,kd ----------------
__global__ void k1_proj(const float* __restrict__ t,
                        const float* __restrict__ Qd, const float* __restrict__ Kd,
                        const float* __restrict__ Qs, const float* __restrict__ Ks) {
    int b = blockIdx.y, n = blockIdx.x;
    __shared__ float ts[DD];
    int tid = threadIdx.x;                  // 384 threads
    if (tid < DD) ts[tid] = t[(b*NN+n)*DD + tid];
    __syncthreads();
    const float* W; int ld, col; float* outp;
    if (tid < 64)       { W = Qs; ld = DSIMC; col = tid;     outp = &g_q [(b*NN+n)*DSIMC + col]; }
    else if (tid < 128) { W = Ks; ld = DSIMC; col = tid-64;  outp = &g_k [(b*NN+n)*DSIMC + col]; }
    else if (tid < 256) { W = Qd; ld = DDIRC; col = tid-128; outp = &g_qd[(b*NN+n)*DDIRC + col]; }
    else                { W = Kd; ld = DDIRC; col = tid-256; outp = &g_kd[(b*NN+n)*DDIRC + col]; }
    float acc = 0.f;
    #pragma unroll 8
    for (int r = 0; r < DD; r++) acc += ts[r] * W[r*ld + col];
    *outp = acc;
}

// ---------------- K2: symmetrized s + off-diagonal sum / sumsq ----------------
__global__ void k2_sim() {
    int b = blockIdx.y, i = blockIdx.x, j = threadIdx.x;   // 384 threads
    __shared__ float qi[DSIMC], ki[DSIMC];
    __shared__ float red0[12], red1[12];
    if (j < DSIMC)        qi[j]       = g_q[(b*NN+i)*DSIMC + j];
    else if (j < 2*DSIMC) ki[j-DSIMC] = g_k[(b*NN+i)*DSIMC + (j-DSIMC)];
    __syncthreads();
    const float4* kj = (const float4*)&g_k[(b*NN+j)*DSIMC];
    const float4* qj = (const float4*)&g_q[(b*NN+j)*DSIMC];
    float acc = 0.f;
    #pragma unroll
    for (int r4 = 0; r4 < DSIMC/4; r4++) {
        float4 kv = kj[r4], qv = qj[r4];
        acc += qi[4*r4+0]*kv.x + qi[4*r4+1]*kv.y + qi[4*r4+2]*kv.z + qi[4*r4+3]*kv.w;
        acc += ki[4*r4+0]*qv.x + ki[4*r4+1]*qv.y + ki[4*r4+2]*qv.z + ki[4*r4+3]*qv.w;
    }
    float s = acc * 0.0625f;   // 0.5 / sqrt(64)
    g_s[(b*NN+i)*NN + j] = s;
    float sv = (j == i) ? 0.f : s;
    float s2 = sv * sv;
    #pragma unroll
    for (int o = 16; o; o >>= 1) {
        sv += __shfl_xor_sync(~0u, sv, o);
        s2 += __shfl_xor_sync(~0u, s2, o);
    }
    int w = j >> 5, l = j & 31;
    if (!l) { red0[w] = sv; red1[w] = s2; }
    __syncthreads();
    if (j == 0) {
        double a = 0, c = 0;
        for (int w2 = 0; w2 < 12; w2++) { a += (double)red0[w2]; c += (double)red1[w2]; }
        atomicAdd(&g_stats[b*2+0], a);
        atomicAdd(&g_stats[b*2+1], c);
    }
}

// ---------------- K3: per-row exp-sum -> m ----------------
__global__ void k3_m(const float* __restrict__ al, const float* __restrict__ bl) {
    int b = blockIdx.y, i = blockIdx.x, j = threadIdx.x;   // 384 threads
    __shared__ float red[12];
    const float cnt = (float)(NN*(NN-1));
    float mu  = (float)(g_stats[b*2+0] / cnt);
    float var = (float)(g_stats[b*2+1] / cnt) - mu*mu;
    float inv = rsqrtf(var + EPSF);
    float a = al[0], bv = bl[0];
    float s  = g_s[(b*NN+i)*NN + j];
    float ts = a * ((s - mu) * inv) + bv;
    float e  = expf(ts);   // GAMMA = 1
    #pragma unroll
    for (int o = 16; o; o >>= 1) e += __shfl_xor_sync(~0u, e, o);
    int w = j >> 5, l = j & 31;
    if (!l) red[w] = e;
    __syncthreads();
    if (j == 0) {
        float E = 0.f;
        for (int w2 = 0; w2 < 12; w2++) E += red[w2];
        g_m[b*NN+i] = 1.f / (E + EPSF);
    }
}

// ---------------- K5: heavy fused gate + aggregation ----------------
__global__ void __launch_bounds__(256) k5_heavy(
    const float* __restrict__ t, const float* __restrict__ al,
    const float* __restrict__ bl, float* __restrict__ outp)
{
    const int b = blockIdx.y, i = blockIdx.x;
    const int tid  = threadIdx.x;
    const int lane = tid & 31, wid = tid >> 5;
    const int T = lane & 3, grp = lane >> 2;

    __shared__ float sm_ti[DD];
    __shared__ float sm_qdi[DDIRC], sm_kdi[DDIRC];
    __shared__ float sm_alpha[NN];
    __shared__ __align__(16) __nv_bfloat16 sm_U[16*136];
    __shared__ float sm_t[16*260];
    __shared__ float sm_red[8];

    // ---- prologue loads ----
    if (tid < DD) sm_ti[tid] = t[(b*NN+i)*DD + tid];
    if (tid < DDIRC)        sm_qdi[tid]        = g_qd[(b*NN+i)*DDIRC + tid];
    else if (tid < 2*DDIRC) sm_kdi[tid-DDIRC]  = g_kd[(b*NN+i)*DDIRC + tid - DDIRC];

    // ---- alpha row in smem ----
    const float cnt = (float)(NN*(NN-1));
    float mu  = (float)(g_stats[b*2+0] / cnt);
    float var = (float)(g_stats[b*2+1] / cnt) - mu*mu;
    float inv = rsqrtf(var + EPSF);
    float aa = al[0], bv = bl[0];
    float rs = 0.f;
    for (int j = tid; j < NN; j += 256) {
        float s  = g_s[(b*NN+i)*NN + j];
        float ts = aa * ((s - mu) * inv) + bv;
        float A  = 1.f / (1.f + expf(-ts));
        float w  = A * g_m[b*NN + j];
        sm_alpha[j] = A * w;
        rs += w;                                // rowsum of w includes diagonal
    }
    #pragma unroll
    for (int o = 16; o; o >>= 1) rs += __shfl_xor_sync(~0u, rs, o);
    if (!lane) sm_red[wid] = rs;
    __syncthreads();
    float rstot = 0.f;
    #pragma unroll
    for (int w2 = 0; w2 < 8; w2++) rstot += sm_red[w2];
    float rinv = 1.f / (rstot + DELTAF);
    for (int j = tid; j < NN; j += 256)
        sm_alpha[j] = (j == i) ? 0.f : sm_alpha[j] * rinv;

    // ---- preload B fragments (Vd) into registers: breg[kc][f][2] ----
    uint32_t breg[8][4][2];
    const int warpD = wid * 32;
    #pragma unroll
    for (int kc = 0; kc < 8; kc++)
        #pragma unroll
        for (int f = 0; f < 4; f++) {
            int n = warpD + 8*f + grp;
            const __nv_bfloat16* base = &g_vdt[n*DDIRC + kc*16 + 2*T];
            breg[kc][f][0] = *(const uint32_t*)(base);
            breg[kc][f][1] = *(const uint32_t*)(base + 8);
        }

    float acc[4][2] = {};

    const int jj = tid >> 4;           // 0..15 (row within tile)
    const int rb = (tid & 15) * 8;     // U-build r base
    const int db = (tid & 15) * 16;    // t-tile d base

    for (int jt = 0; jt < NN/16; jt++) {
        const int j0 = jt * 16;
        __syncthreads();
        // ---- build U tile (bf16) + t tile (f32) in smem ----
        {
            int j = j0 + jj;
            const float4* kdj = (const float4*)&g_kd[(b*NN+j)*DDIRC + rb];
            const float4* qdj = (const float4*)&g_qd[(b*NN+j)*DDIRC + rb];
            float4 kv0 = kdj[0], kv1 = kdj[1];
            float4 qv0 = qdj[0], qv1 = qdj[1];
            float kd_[8] = {kv0.x,kv0.y,kv0.z,kv0.w,kv1.x,kv1.y,kv1.z,kv1.w};
            float qd_[8] = {qv0.x,qv0.y,qv0.z,qv0.w,qv1.x,qv1.y,qv1.z,qv1.w};
            float u[8];
            #pragma unroll
            for (int v = 0; v < 8; v++)
                u[v] = sm_qdi[rb+v]*kd_[v] - qd_[v]*sm_kdi[rb+v];
            __nv_bfloat162* dst = (__nv_bfloat162*)&sm_U[jj*136 + rb];
            #pragma unroll
            for (int p = 0; p < 4; p++)
                dst[p] = __floats2bfloat162_rn(u[2*p], u[2*p+1]);

            const float4* tj = (const float4*)&t[(b*NN+j)*DD + db];
            float4 t0 = tj[0], t1 = tj[1], t2 = tj[2], t3 = tj[3];
            float* td = &sm_t[jj*260 + db];
            *(float4*)(td+0)  = t0;  *(float4*)(td+4)  = t1;
            *(float4*)(td+8)  = t2;  *(float4*)(td+12) = t3;
        }
        __syncthreads();

        // ---- MMA: Delta tile (16 j x 32 d per warp) ----
        float c[4][4] = {};
        #pragma unroll
        for (int kc = 0; kc < 8; kc++) {
            const __nv_bfloat16* u0 = &sm_U[grp*136     + kc*16 + 2*T];
            const __nv_bfloat16* u1 = &sm_U[(grp+8)*136 + kc*16 + 2*T];
            uint32_t a0 = *(const uint32_t*)(u0);
            uint32_t a1 = *(const uint32_t*)(u1);
            uint32_t a2 = *(const uint32_t*)(u0 + 8);
            uint32_t a3 = *(const uint32_t*)(u1 + 8);
            #pragma unroll
            for (int f = 0; f < 4; f++)
                asm volatile(
                    "mma.sync.aligned.m16n8k16.row.col.f32.bf16.bf16.f32 "
                    "{%0,%1,%2,%3}, {%4,%5,%6,%7}, {%8,%9}, {%0,%1,%2,%3};"
                    : "+f"(c[f][0]), "+f"(c[f][1]), "+f"(c[f][2]), "+f"(c[f][3])
                    : "r"(a0), "r"(a1), "r"(a2), "r"(a3),
                      "r"(breg[kc][f][0]), "r"(breg[kc][f][1]));
        }

        // ---- epilogue: sigmoid, alpha, (t_i - t_j), accumulate over j ----
        float ar0 = sm_alpha[j0 + grp];
        float ar1 = sm_alpha[j0 + grp + 8];
        #pragma unroll
        for (int f = 0; f < 4; f++) {
            int d0 = warpD + 8*f + 2*T;
            float ti0 = sm_ti[d0], ti1 = sm_ti[d0+1];
            float tj00 = sm_t[grp*260 + d0],       tj01 = sm_t[grp*260 + d0 + 1];
            float tj10 = sm_t[(grp+8)*260 + d0],   tj11 = sm_t[(grp+8)*260 + d0 + 1];
            float g00 = 1.f/(1.f + __expf(-c[f][0]));   // row grp,   col d0
            float g01 = 1.f/(1.f + __expf(-c[f][1]));   // row grp,   col d0+1
            float g10 = 1.f/(1.f + __expf(-c[f][2]));   // row grp+8, col d0
            float g11 = 1.f/(1.f + __expf(-c[f][3]));   // row grp+8, col d0+1
            acc[f][0] += ar0*g00*(ti0 - tj00) + ar1*g10*(ti0 - tj10);
            acc[f][1] += ar0*g01*(ti1 - tj01) + ar1*g11*(ti1 - tj11);
        }
    }

    // ---- reduce over the 8 row-groups (lanes differing in grp bits) ----
    #pragma unroll
    for (int f = 0; f < 4; f++)
        #pragma unroll
        for (int e = 0; e < 2; e++) {
            float v = acc[f][e];
            v += __shfl_xor_sync(~0u, v, 4);
            v += __shfl_xor_sync(~0u, v, 8);
            v += __shfl_xor_sync(~0u, v, 16);
            acc[f][e] = v;
        }
    if (grp == 0) {
        #pragma unroll
        for (int f = 0; f < 4; f++) {
            int d0 = warpD + 8*f + 2*T;
            outp[(b*NN+i)*DD + d0]   = sm_ti[d0]   - acc[f][0];
            outp[(b*NN+i)*DD + d0+1] = sm_ti[d0+1] - acc[f][1];
        }
    }
}

// ---------------- launch ----------------
extern "C" void kernel_launch(void* const* d_in, const int* in_sizes, int n_in,
                              void* d_out, int out_size) {
    const float* t  = (const float*)d_in[0];
    const float* Qd = (const float*)d_in[1];
    const float* Kd = (const float*)d_in[2];
    const float* Vd = (const float*)d_in[3];
    const float* Qs = (const float*)d_in[4];
    const float* Ks = (const float*)d_in[5];
    const float* al = (const float*)d_in[6];
    const float* bl = (const float*)d_in[7];
    float* outp = (float*)d_out;

    dim3 gridBN(NN, BB);
    k0_init<<<64, 256>>>(Vd);
    k1_proj<<<gridBN, 384>>>(t, Qd, Kd, Qs, Ks);
    k2_sim<<<gridBN, 384>>>();
    k3_m<<<gridBN, 384>>>(al, bl);
    k5_heavy<<<gridBN, 256>>>(t, al, bl, outp);
}